// round 13
// baseline (speedup 1.0000x reference)
#include <cuda_runtime.h>
#include <cuda_bf16.h>
#include <math.h>
#include <cstdint>

#define BATCH   32
#define TT      256
#define EE      256
#define CC      256
#define SLEN    192
#define NROWS   (BATCH * SLEN)      // 6144
#define NSTEPS  12
#define K3      768                 // stacked K: [hi|hi|lo] . [hi|lo|hi]
#define KCH     16                  // k per chunk
#define NCH     (K3 / KCH)          // 48
#define NSTG    3                   // pipeline stages
#define OFFSET  40.0f
#define TOTAL_COUNT 71616.0
#define SST     24                  // smem row stride (bf16): 48B; 3r mod 8 distinct -> ldmatrix conflict-free

// ---------------- scratch ----------------
__device__ float          g_P[NROWS * CC];           // fp32 projections (6 MB)
__device__ __nv_bfloat16  g_A3[(size_t)NROWS * K3];  // 9 MB
__device__ __nv_bfloat16  g_B3[(size_t)NROWS * K3];  // 9 MB
__device__ float          g_head[NROWS];
__device__ float          g_tail[NROWS * 11];
__device__ float          g_pos [NROWS * NSTEPS];

// ---------------- asm helpers ----------------
#define CP_ASYNC16(sa, gp) \
    asm volatile("cp.async.cg.shared.global [%0], [%1], 16;" :: "r"(sa), "l"(gp))
#define CP_COMMIT() asm volatile("cp.async.commit_group;" ::: "memory")
#define CP_WAIT(n)  asm volatile("cp.async.wait_group %0;" :: "n"(n) : "memory")
#define LDMX4(r0, r1, r2, r3, addr) \
    asm volatile("ldmatrix.sync.aligned.m8n8.x4.shared.b16 {%0,%1,%2,%3}, [%4];" \
                 : "=r"(r0), "=r"(r1), "=r"(r2), "=r"(r3) : "r"(addr))

__device__ __forceinline__ uint32_t smem_u32(const void* p) {
    return (uint32_t)__cvta_generic_to_shared(p);
}
__device__ __forceinline__ void mma16816(float* d, const uint32_t* a, const uint32_t* b) {
    asm volatile(
        "mma.sync.aligned.m16n8k16.row.col.f32.bf16.bf16.f32 "
        "{%0,%1,%2,%3}, {%4,%5,%6,%7}, {%8,%9}, {%0,%1,%2,%3};"
        : "+f"(d[0]), "+f"(d[1]), "+f"(d[2]), "+f"(d[3])
        : "r"(a[0]), "r"(a[1]), "r"(a[2]), "r"(a[3]), "r"(b[0]), "r"(b[1]));
}

// ---------------------------------------------------------------------------
// 1) build_P: P = emb_slice @ W (fp32); writes g_P AND split-bf16 A3 rows
//    [hi|hi|lo]; zeroes head/tail. grid 192, block 256, 32 rows/blk.
// ---------------------------------------------------------------------------
__global__ void __launch_bounds__(256) build_P(const float* __restrict__ emb,
                                               const float* __restrict__ W) {
    __shared__ float stage[32 * 66];
    int tid = threadIdx.x;
    int r0  = blockIdx.x * 32;
    int b   = r0 / SLEN;
    int u0  = r0 - b * SLEN;

    float acc[32];
    #pragma unroll
    for (int i = 0; i < 32; ++i) acc[i] = 0.f;

    for (int e0 = 0; e0 < EE; e0 += 64) {
        __syncthreads();
        for (int idx = tid; idx < 32 * 64; idx += 256) {
            int i = idx >> 6, e = idx & 63;
            stage[i * 66 + e] = emb[((b * TT) + 64 + u0 + i) * EE + e0 + e];
        }
        __syncthreads();
        #pragma unroll 4
        for (int e = 0; e < 64; ++e) {
            float w = W[(e0 + e) * CC + tid];
            #pragma unroll
            for (int i = 0; i < 32; ++i) acc[i] += stage[i * 66 + e] * w;
        }
    }
    #pragma unroll
    for (int i = 0; i < 32; ++i) {
        int r = r0 + i;
        float x = acc[i];
        g_P[r * CC + tid] = x;
        __nv_bfloat16 hi = __float2bfloat16(x);
        __nv_bfloat16 lo = __float2bfloat16(x - __bfloat162float(hi));
        size_t base = (size_t)r * K3;
        g_A3[base + tid]       = hi;
        g_A3[base + 256 + tid] = hi;
        g_A3[base + 512 + tid] = lo;
    }
    if (tid < 32) g_head[r0 + tid] = 0.f;
    for (int t = tid; t < 32 * 11; t += 256) g_tail[r0 * 11 + t] = 0.f;
}

// ---------------------------------------------------------------------------
// 2) split_B: B3 row = [hi(C) | lo(C) | hi(C)] from gathered ctx.
// ---------------------------------------------------------------------------
__global__ void __launch_bounds__(256) split_B(const float* __restrict__ ctx) {
    int c = blockIdx.x, tid = threadIdx.x;
    int j = c / SLEN, v = c - j * SLEN;
    float x = ctx[((j * TT) + 63 + v) * CC + tid];
    __nv_bfloat16 hi = __float2bfloat16(x);
    __nv_bfloat16 lo = __float2bfloat16(x - __bfloat162float(hi));
    size_t base = (size_t)c * K3;
    g_B3[base + tid]       = hi;
    g_B3[base + 256 + tid] = lo;
    g_B3[base + 512 + tid] = hi;
}

// ---------------------------------------------------------------------------
// 3) positives: g_pos[r][s] = dot(P[r], ctx[b][63+u-s]) fp32. 1 warp/row.
// ---------------------------------------------------------------------------
__global__ void __launch_bounds__(256) positives(const float* __restrict__ ctx) {
    int tid = threadIdx.x, wid = tid >> 5, lane = tid & 31;
    int r = blockIdx.x * 8 + wid;
    int b = r / SLEN, u = r - b * SLEN;

    float p[8];
    #pragma unroll
    for (int i = 0; i < 8; ++i) p[i] = g_P[r * CC + lane + i * 32];

    int smax = (u < 11) ? u : 11;
    for (int s = 0; s <= smax; ++s) {
        const float* crow = ctx + ((b * TT) + 63 + (u - s)) * CC;
        float acc = 0.f;
        #pragma unroll
        for (int i = 0; i < 8; ++i) acc += p[i] * crow[lane + i * 32];
        #pragma unroll
        for (int off = 16; off; off >>= 1)
            acc += __shfl_down_sync(0xffffffffu, acc, off);
        if (lane == 0) g_pos[r * NSTEPS + s] = acc;
    }
}

// ---------------------------------------------------------------------------
// 4) gemm_mma: bf16 mma.sync GEMM, 3-stage cp.async pipeline, KCH=16.
//    128x128 tile/CTA, 8 warps (2Mx4N). grid (48,48), block 256.
//    smem: 3 stages x (sA+sB) x 128 x 24 bf16 = 36864 B.
// ---------------------------------------------------------------------------
__global__ void __launch_bounds__(256) gemm_mma() {
    __shared__ __nv_bfloat16 sA[NSTG][128 * SST];
    __shared__ __nv_bfloat16 sB[NSTG][128 * SST];

    int tid  = threadIdx.x;
    int wid  = tid >> 5;
    int lane = tid & 31;
    int g    = lane >> 2;
    int tg   = lane & 3;
    int wM   = wid & 1;
    int wN   = wid >> 1;
    int row0 = blockIdx.y * 128;
    int col0 = blockIdx.x * 128;

    // 512 16B transfers per chunk, 2 per thread: idx<256 -> A, else B
    int rrL[2], cuL[2], isB[2];
    #pragma unroll
    for (int i = 0; i < 2; ++i) {
        int idx = tid + i * 256;
        isB[i] = idx >> 8;
        int sub = idx & 255;
        rrL[i] = sub >> 1;
        cuL[i] = (sub & 1) * 8;
    }

    auto issue_load = [&](int ch, int st) {
        #pragma unroll
        for (int i = 0; i < 2; ++i) {
            int rr = rrL[i], cu = cuL[i];
            if (isB[i] == 0) {
                uint32_t sa = smem_u32(&sA[st][rr * SST + cu]);
                CP_ASYNC16(sa, &g_A3[(size_t)(row0 + rr) * K3 + ch * KCH + cu]);
            } else {
                uint32_t sa = smem_u32(&sB[st][rr * SST + cu]);
                CP_ASYNC16(sa, &g_B3[(size_t)(col0 + rr) * K3 + ch * KCH + cu]);
            }
        }
        CP_COMMIT();
    };

    float d[4][4][4];
    #pragma unroll
    for (int mi = 0; mi < 4; ++mi)
        #pragma unroll
        for (int ni = 0; ni < 4; ++ni)
            #pragma unroll
            for (int q = 0; q < 4; ++q) d[mi][ni][q] = 0.f;

    issue_load(0, 0);
    issue_load(1, 1);

    int lr  = lane & 15;
    int lcb = (lane >> 4) * 8;

    for (int ch = 0; ch < NCH; ++ch) {
        int st = ch % NSTG;
        CP_WAIT(1);                         // chunk ch resident
        __syncthreads();                    // all warps past compute(ch-1), data visible
        if (ch + 2 < NCH) issue_load(ch + 2, (ch + 2) % NSTG);
        else CP_COMMIT();                   // dummy group keeps wait arithmetic exact

        uint32_t bfr[2][4];
        #pragma unroll
        for (int pr = 0; pr < 2; ++pr) {
            uint32_t addr = smem_u32(&sB[st][(wN * 32 + pr * 16 + lr) * SST + lcb]);
            LDMX4(bfr[pr][0], bfr[pr][1], bfr[pr][2], bfr[pr][3], addr);
        }
        #pragma unroll
        for (int mi = 0; mi < 4; ++mi) {
            uint32_t afr[4];
            uint32_t addr = smem_u32(&sA[st][(wM * 64 + mi * 16 + lr) * SST + lcb]);
            LDMX4(afr[0], afr[1], afr[2], afr[3], addr);
            #pragma unroll
            for (int pr = 0; pr < 2; ++pr) {
                uint32_t b0[2] = {bfr[pr][0], bfr[pr][2]};
                uint32_t b1[2] = {bfr[pr][1], bfr[pr][3]};
                mma16816(d[mi][pr * 2],     afr, b0);
                mma16816(d[mi][pr * 2 + 1], afr, b1);
            }
        }
    }

    // ---- epilogue: exp + head/tail ----
    float headLo[4] = {0, 0, 0, 0}, headHi[4] = {0, 0, 0, 0};
    #pragma unroll
    for (int mi = 0; mi < 4; ++mi) {
        int rLo = row0 + wM * 64 + mi * 16 + g;
        int rHi = rLo + 8;
        #pragma unroll
        for (int ni = 0; ni < 4; ++ni) {
            int c0c = col0 + wN * 32 + ni * 8 + tg * 2;
            #pragma unroll
            for (int q = 0; q < 2; ++q) {
                int cc = c0c + q;
                int v  = cc % SLEN;
                float eLo = __expf(d[mi][ni][q]     - OFFSET);
                float eHi = __expf(d[mi][ni][q + 2] - OFFSET);
                if (v < 181) { headLo[mi] += eLo; headHi[mi] += eHi; }
                else {
                    atomicAdd(&g_tail[rLo * 11 + (v - 181)], eLo);
                    atomicAdd(&g_tail[rHi * 11 + (v - 181)], eHi);
                }
            }
        }
    }
    #pragma unroll
    for (int mi = 0; mi < 4; ++mi) {
        float lo = headLo[mi], hi = headHi[mi];
        lo += __shfl_down_sync(0xffffffffu, lo, 2, 4);
        lo += __shfl_down_sync(0xffffffffu, lo, 1, 4);
        hi += __shfl_down_sync(0xffffffffu, hi, 2, 4);
        hi += __shfl_down_sync(0xffffffffu, hi, 1, 4);
        if (tg == 0) {
            int rLo = row0 + wM * 64 + mi * 16 + g;
            atomicAdd(&g_head[rLo],     lo);
            atomicAdd(&g_head[rLo + 8], hi);
        }
    }
}

// ---------------------------------------------------------------------------
// 5) finalize: S_s = head + prefix(tails) (addition only). 1024 threads.
// ---------------------------------------------------------------------------
__global__ void __launch_bounds__(1024) finalize(float* __restrict__ out, int out_size) {
    __shared__ double sred[1024];
    __shared__ float slogN[NSTEPS];
    int tid = threadIdx.x;
    if (tid < NSTEPS) slogN[tid] = logf((float)(BATCH * (SLEN - tid)));
    __syncthreads();

    double s = 0.0;
    for (int r = tid; r < NROWS; r += 1024) {
        float hd = g_head[r];
        float pref[12];
        pref[0] = 0.f;
        #pragma unroll
        for (int t = 0; t < 11; ++t) pref[t + 1] = pref[t] + g_tail[r * 11 + t];
        int u = r % SLEN;
        int smax = (u < 11) ? u : 11;
        for (int st = 0; st <= smax; ++st) {
            float S = hd + pref[11 - st];
            float lse = OFFSET + logf(fmaxf(S, 1e-35f)) - slogN[st];
            s += (double)(g_pos[r * NSTEPS + st] - lse);
        }
    }
    sred[tid] = s;
    __syncthreads();
    for (int k = 512; k > 0; k >>= 1) {
        if (tid < k) sred[tid] += sred[tid + k];
        __syncthreads();
    }
    float val = (float)(-sred[0] / TOTAL_COUNT);
    for (int i = tid; i < out_size; i += 1024) out[i] = val;
}

// ---------------------------------------------------------------------------
extern "C" void kernel_launch(void* const* d_in, const int* in_sizes, int n_in,
                              void* d_out, int out_size) {
    int wIdx = -1;
    for (int i = 0; i < n_in; ++i)
        if (in_sizes[i] == EE * CC) { wIdx = i; break; }
    if (wIdx < 0) wIdx = 2;
    int others[2]; int no = 0;
    for (int i = 0; i < n_in && no < 2; ++i)
        if (i != wIdx) others[no++] = i;

    const float* embeddings = (const float*)d_in[others[0]];  // (32,256,256)
    const float* contexts   = (const float*)d_in[others[1]];  // (32,256,256)
    const float* W          = (const float*)d_in[wIdx];       // (256,256)
    float* out = (float*)d_out;

    build_P<<<NROWS / 32, 256>>>(embeddings, W);
    split_B<<<NROWS, 256>>>(contexts);
    positives<<<NROWS / 8, 256>>>(contexts);
    gemm_mma<<<dim3(48, 48), 256>>>();
    finalize<<<1, 1024>>>(out, out_size);
}

// round 14
// speedup vs baseline: 1.1828x; 1.1828x over previous
#include <cuda_runtime.h>
#include <cuda_bf16.h>
#include <math.h>
#include <cstdint>

#define BATCH   32
#define TT      256
#define EE      256
#define CC      256
#define SLEN    192
#define NROWS   (BATCH * SLEN)      // 6144
#define NSTEPS  12
#define K3      768                 // stacked K: [hi|hi|lo] . [hi|lo|hi]
#define KCH     32                  // k per chunk
#define NCH     (K3 / KCH)          // 24
#define OFFSET  40.0f
#define TOTAL_COUNT 71616.0
#define SST     40                  // smem row stride (bf16): 80B

// ---------------- scratch ----------------
__device__ float          g_P[NROWS * CC];           // fp32 projections (6 MB)
__device__ __nv_bfloat16  g_A3[(size_t)NROWS * K3];  // 9 MB
__device__ __nv_bfloat16  g_B3[(size_t)NROWS * K3];  // 9 MB
__device__ float          g_head[NROWS];
__device__ float          g_tail[NROWS * 11];
__device__ float          g_pos [NROWS * NSTEPS];

// ---------------- asm helpers ----------------
#define CP_ASYNC16(sa, gp) \
    asm volatile("cp.async.cg.shared.global [%0], [%1], 16;" :: "r"(sa), "l"(gp))
#define CP_COMMIT() asm volatile("cp.async.commit_group;" ::: "memory")
#define CP_WAIT0()  asm volatile("cp.async.wait_group 0;" ::: "memory")
#define LDMX4(r0, r1, r2, r3, addr) \
    asm volatile("ldmatrix.sync.aligned.m8n8.x4.shared.b16 {%0,%1,%2,%3}, [%4];" \
                 : "=r"(r0), "=r"(r1), "=r"(r2), "=r"(r3) : "r"(addr))

__device__ __forceinline__ uint32_t smem_u32(const void* p) {
    return (uint32_t)__cvta_generic_to_shared(p);
}
__device__ __forceinline__ void mma16816(float* d, const uint32_t* a, const uint32_t* b) {
    asm volatile(
        "mma.sync.aligned.m16n8k16.row.col.f32.bf16.bf16.f32 "
        "{%0,%1,%2,%3}, {%4,%5,%6,%7}, {%8,%9}, {%0,%1,%2,%3};"
        : "+f"(d[0]), "+f"(d[1]), "+f"(d[2]), "+f"(d[3])
        : "r"(a[0]), "r"(a[1]), "r"(a[2]), "r"(a[3]), "r"(b[0]), "r"(b[1]));
}

// ---------------------------------------------------------------------------
// 1) build_P: P = emb_slice @ W; writes g_P AND split-bf16 A3 [hi|hi|lo];
//    zeroes head/tail. grid 192, block 256, 32 rows/blk.
// ---------------------------------------------------------------------------
__global__ void __launch_bounds__(256) build_P(const float* __restrict__ emb,
                                               const float* __restrict__ W) {
    __shared__ float stage[32 * 66];
    int tid = threadIdx.x;
    int r0  = blockIdx.x * 32;
    int b   = r0 / SLEN;
    int u0  = r0 - b * SLEN;

    float acc[32];
    #pragma unroll
    for (int i = 0; i < 32; ++i) acc[i] = 0.f;

    for (int e0 = 0; e0 < EE; e0 += 64) {
        __syncthreads();
        for (int idx = tid; idx < 32 * 64; idx += 256) {
            int i = idx >> 6, e = idx & 63;
            stage[i * 66 + e] = emb[((b * TT) + 64 + u0 + i) * EE + e0 + e];
        }
        __syncthreads();
        #pragma unroll 4
        for (int e = 0; e < 64; ++e) {
            float w = W[(e0 + e) * CC + tid];
            #pragma unroll
            for (int i = 0; i < 32; ++i) acc[i] += stage[i * 66 + e] * w;
        }
    }
    #pragma unroll
    for (int i = 0; i < 32; ++i) {
        int r = r0 + i;
        float x = acc[i];
        g_P[r * CC + tid] = x;
        __nv_bfloat16 hi = __float2bfloat16(x);
        __nv_bfloat16 lo = __float2bfloat16(x - __bfloat162float(hi));
        size_t base = (size_t)r * K3;
        g_A3[base + tid]       = hi;
        g_A3[base + 256 + tid] = hi;
        g_A3[base + 512 + tid] = lo;
    }
    if (tid < 32) g_head[r0 + tid] = 0.f;
    for (int t = tid; t < 32 * 11; t += 256) g_tail[r0 * 11 + t] = 0.f;
}

// ---------------------------------------------------------------------------
// 2) split_B: B3 row = [hi(C) | lo(C) | hi(C)] from gathered ctx.
// ---------------------------------------------------------------------------
__global__ void __launch_bounds__(256) split_B(const float* __restrict__ ctx) {
    int c = blockIdx.x, tid = threadIdx.x;
    int j = c / SLEN, v = c - j * SLEN;
    float x = ctx[((j * TT) + 63 + v) * CC + tid];
    __nv_bfloat16 hi = __float2bfloat16(x);
    __nv_bfloat16 lo = __float2bfloat16(x - __bfloat162float(hi));
    size_t base = (size_t)c * K3;
    g_B3[base + tid]       = hi;
    g_B3[base + 256 + tid] = lo;
    g_B3[base + 512 + tid] = hi;
}

// ---------------------------------------------------------------------------
// 3) positives: g_pos[r][s] = dot(P[r], ctx[b][63+u-s]) fp32. 1 warp/row.
// ---------------------------------------------------------------------------
__global__ void __launch_bounds__(256) positives(const float* __restrict__ ctx) {
    int tid = threadIdx.x, wid = tid >> 5, lane = tid & 31;
    int r = blockIdx.x * 8 + wid;
    int b = r / SLEN, u = r - b * SLEN;

    float p[8];
    #pragma unroll
    for (int i = 0; i < 8; ++i) p[i] = g_P[r * CC + lane + i * 32];

    int smax = (u < 11) ? u : 11;
    for (int s = 0; s <= smax; ++s) {
        const float* crow = ctx + ((b * TT) + 63 + (u - s)) * CC;
        float acc = 0.f;
        #pragma unroll
        for (int i = 0; i < 8; ++i) acc += p[i] * crow[lane + i * 32];
        #pragma unroll
        for (int off = 16; off; off >>= 1)
            acc += __shfl_down_sync(0xffffffffu, acc, off);
        if (lane == 0) g_pos[r * NSTEPS + s] = acc;
    }
}

// ---------------------------------------------------------------------------
// 4) gemm_mma: bf16 mma.sync GEMM, KCH=32, 2-stage cp.async, 1 sync/chunk,
//    ALL addressing hoisted out of the main loop.
//    128x128 tile/CTA, 8 warps (2Mx4N). grid (48,48), block 256.
//    smem: 2 x (sA+sB) x 128 x 40 bf16 = 40960 B.
// ---------------------------------------------------------------------------
__global__ void __launch_bounds__(256) gemm_mma() {
    __shared__ __nv_bfloat16 sA[2][128 * SST];
    __shared__ __nv_bfloat16 sB[2][128 * SST];

    int tid  = threadIdx.x;
    int wid  = tid >> 5;
    int lane = tid & 31;
    int g    = lane >> 2;
    int tg   = lane & 3;
    int wM   = wid & 1;
    int wN   = wid >> 1;
    int row0 = blockIdx.y * 128;
    int col0 = blockIdx.x * 128;

    // ---- hoisted load addressing: 4 slots/thread (1024 x 16B per chunk) ----
    const char* gp[4];          // global src, advanced by KCH*2 per chunk
    uint32_t    sa[2][4];       // smem dst per stage
    #pragma unroll
    for (int i = 0; i < 4; ++i) {
        int idx = tid + i * 256;           // 0..1023
        int isB = idx >> 9;
        int sub = idx & 511;
        int rr  = sub >> 2;                // 0..127
        int cu  = (sub & 3) * 8;           // bf16 offset
        if (isB == 0) {
            gp[i] = (const char*)&g_A3[(size_t)(row0 + rr) * K3 + cu];
            sa[0][i] = smem_u32(&sA[0][rr * SST + cu]);
            sa[1][i] = smem_u32(&sA[1][rr * SST + cu]);
        } else {
            gp[i] = (const char*)&g_B3[(size_t)(col0 + rr) * K3 + cu];
            sa[0][i] = smem_u32(&sB[0][rr * SST + cu]);
            sa[1][i] = smem_u32(&sB[1][rr * SST + cu]);
        }
    }

    // ---- hoisted fragment addressing ----
    int lr  = lane & 15;
    int lcb = (lane >> 4) * 8;
    uint32_t aB[2], bB[2];      // per-stage warp bases
    aB[0] = smem_u32(&sA[0][(wM * 64 + lr) * SST + lcb]);
    aB[1] = smem_u32(&sA[1][(wM * 64 + lr) * SST + lcb]);
    bB[0] = smem_u32(&sB[0][(wN * 32 + lr) * SST + lcb]);
    bB[1] = smem_u32(&sB[1][(wN * 32 + lr) * SST + lcb]);

    float d[4][4][4];
    #pragma unroll
    for (int mi = 0; mi < 4; ++mi)
        #pragma unroll
        for (int ni = 0; ni < 4; ++ni)
            #pragma unroll
            for (int q = 0; q < 4; ++q) d[mi][ni][q] = 0.f;

    // preload chunk 0 into stage 0
    #pragma unroll
    for (int i = 0; i < 4; ++i) { CP_ASYNC16(sa[0][i], gp[i]); gp[i] += KCH * 2; }
    CP_COMMIT();

    for (int ch = 0; ch < NCH; ++ch) {
        int st = ch & 1;
        CP_WAIT0();                         // chunk ch resident (sole group)
        __syncthreads();                    // compute(ch-1) done; data visible
        if (ch + 1 < NCH) {
            #pragma unroll
            for (int i = 0; i < 4; ++i) { CP_ASYNC16(sa[st ^ 1][i], gp[i]); gp[i] += KCH * 2; }
            CP_COMMIT();
        }

        #pragma unroll
        for (int ks = 0; ks < 2; ++ks) {    // 2 k-steps of 16
            uint32_t kOff = ks * 16 * 2;    // bytes
            uint32_t bfr[2][4];
            #pragma unroll
            for (int pr = 0; pr < 2; ++pr) {
                LDMX4(bfr[pr][0], bfr[pr][1], bfr[pr][2], bfr[pr][3],
                      bB[st] + pr * (16 * SST * 2) + kOff);
            }
            #pragma unroll
            for (int mi = 0; mi < 4; ++mi) {
                uint32_t afr[4];
                LDMX4(afr[0], afr[1], afr[2], afr[3],
                      aB[st] + mi * (16 * SST * 2) + kOff);
                #pragma unroll
                for (int pr = 0; pr < 2; ++pr) {
                    uint32_t b0[2] = {bfr[pr][0], bfr[pr][2]};
                    uint32_t b1[2] = {bfr[pr][1], bfr[pr][3]};
                    mma16816(d[mi][pr * 2],     afr, b0);
                    mma16816(d[mi][pr * 2 + 1], afr, b1);
                }
            }
        }
    }

    // ---- epilogue: exp + head/tail ----
    float headLo[4] = {0, 0, 0, 0}, headHi[4] = {0, 0, 0, 0};
    #pragma unroll
    for (int mi = 0; mi < 4; ++mi) {
        int rLo = row0 + wM * 64 + mi * 16 + g;
        int rHi = rLo + 8;
        #pragma unroll
        for (int ni = 0; ni < 4; ++ni) {
            int c0c = col0 + wN * 32 + ni * 8 + tg * 2;
            #pragma unroll
            for (int q = 0; q < 2; ++q) {
                int cc = c0c + q;
                int v  = cc % SLEN;
                float eLo = __expf(d[mi][ni][q]     - OFFSET);
                float eHi = __expf(d[mi][ni][q + 2] - OFFSET);
                if (v < 181) { headLo[mi] += eLo; headHi[mi] += eHi; }
                else {
                    atomicAdd(&g_tail[rLo * 11 + (v - 181)], eLo);
                    atomicAdd(&g_tail[rHi * 11 + (v - 181)], eHi);
                }
            }
        }
    }
    #pragma unroll
    for (int mi = 0; mi < 4; ++mi) {
        float lo = headLo[mi], hi = headHi[mi];
        lo += __shfl_down_sync(0xffffffffu, lo, 2, 4);
        lo += __shfl_down_sync(0xffffffffu, lo, 1, 4);
        hi += __shfl_down_sync(0xffffffffu, hi, 2, 4);
        hi += __shfl_down_sync(0xffffffffu, hi, 1, 4);
        if (tg == 0) {
            int rLo = row0 + wM * 64 + mi * 16 + g;
            atomicAdd(&g_head[rLo],     lo);
            atomicAdd(&g_head[rLo + 8], hi);
        }
    }
}

// ---------------------------------------------------------------------------
// 5) finalize: S_s = head + prefix(tails) (addition only). 1024 threads.
// ---------------------------------------------------------------------------
__global__ void __launch_bounds__(1024) finalize(float* __restrict__ out, int out_size) {
    __shared__ double sred[1024];
    __shared__ float slogN[NSTEPS];
    int tid = threadIdx.x;
    if (tid < NSTEPS) slogN[tid] = logf((float)(BATCH * (SLEN - tid)));
    __syncthreads();

    double s = 0.0;
    for (int r = tid; r < NROWS; r += 1024) {
        float hd = g_head[r];
        float pref[12];
        pref[0] = 0.f;
        #pragma unroll
        for (int t = 0; t < 11; ++t) pref[t + 1] = pref[t] + g_tail[r * 11 + t];
        int u = r % SLEN;
        int smax = (u < 11) ? u : 11;
        for (int st = 0; st <= smax; ++st) {
            float S = hd + pref[11 - st];
            float lse = OFFSET + logf(fmaxf(S, 1e-35f)) - slogN[st];
            s += (double)(g_pos[r * NSTEPS + st] - lse);
        }
    }
    sred[tid] = s;
    __syncthreads();
    for (int k = 512; k > 0; k >>= 1) {
        if (tid < k) sred[tid] += sred[tid + k];
        __syncthreads();
    }
    float val = (float)(-sred[0] / TOTAL_COUNT);
    for (int i = tid; i < out_size; i += 1024) out[i] = val;
}

// ---------------------------------------------------------------------------
extern "C" void kernel_launch(void* const* d_in, const int* in_sizes, int n_in,
                              void* d_out, int out_size) {
    int wIdx = -1;
    for (int i = 0; i < n_in; ++i)
        if (in_sizes[i] == EE * CC) { wIdx = i; break; }
    if (wIdx < 0) wIdx = 2;
    int others[2]; int no = 0;
    for (int i = 0; i < n_in && no < 2; ++i)
        if (i != wIdx) others[no++] = i;

    const float* embeddings = (const float*)d_in[others[0]];  // (32,256,256)
    const float* contexts   = (const float*)d_in[others[1]];  // (32,256,256)
    const float* W          = (const float*)d_in[wIdx];       // (256,256)
    float* out = (float*)d_out;

    build_P<<<NROWS / 32, 256>>>(embeddings, W);
    split_B<<<NROWS, 256>>>(contexts);
    positives<<<NROWS / 8, 256>>>(contexts);
    gemm_mma<<<dim3(48, 48), 256>>>();
    finalize<<<1, 1024>>>(out, out_size);
}

// round 15
// speedup vs baseline: 1.4603x; 1.2346x over previous
#include <cuda_runtime.h>
#include <cuda_bf16.h>
#include <math.h>
#include <cstdint>

#define BATCH   32
#define TT      256
#define EE      256
#define CC      256
#define SLEN    192
#define NROWS   (BATCH * SLEN)      // 6144
#define NSTEPS  12
#define K3      512                 // stacked K: [hi|lo] . [hi|hi]  (hihi + lohi)
#define KCH     16                  // k per chunk
#define NCH     (K3 / KCH)          // 32
#define NSTG    3                   // pipeline stages
#define OFFSET  40.0f
#define TOTAL_COUNT 71616.0
#define SST     24                  // smem row stride (bf16): 48B, 3r mod 8 distinct

// ---------------- scratch ----------------
__device__ float          g_P[NROWS * CC];           // fp32 projections (6 MB)
__device__ __nv_bfloat16  g_A3[(size_t)NROWS * K3];  // 6 MB
__device__ __nv_bfloat16  g_B3[(size_t)NROWS * K3];  // 6 MB
__device__ float          g_head[NROWS];
__device__ float          g_tail[NROWS * 11];
__device__ float          g_pos [NROWS * NSTEPS];

// ---------------- asm helpers ----------------
#define CP_ASYNC16(sa, gp) \
    asm volatile("cp.async.cg.shared.global [%0], [%1], 16;" :: "r"(sa), "l"(gp))
#define CP_COMMIT() asm volatile("cp.async.commit_group;" ::: "memory")
#define CP_WAIT1()  asm volatile("cp.async.wait_group 1;" ::: "memory")
#define LDMX4(r0, r1, r2, r3, addr) \
    asm volatile("ldmatrix.sync.aligned.m8n8.x4.shared.b16 {%0,%1,%2,%3}, [%4];" \
                 : "=r"(r0), "=r"(r1), "=r"(r2), "=r"(r3) : "r"(addr))

__device__ __forceinline__ uint32_t smem_u32(const void* p) {
    return (uint32_t)__cvta_generic_to_shared(p);
}
__device__ __forceinline__ void mma16816(float* d, const uint32_t* a, const uint32_t* b) {
    asm volatile(
        "mma.sync.aligned.m16n8k16.row.col.f32.bf16.bf16.f32 "
        "{%0,%1,%2,%3}, {%4,%5,%6,%7}, {%8,%9}, {%0,%1,%2,%3};"
        : "+f"(d[0]), "+f"(d[1]), "+f"(d[2]), "+f"(d[3])
        : "r"(a[0]), "r"(a[1]), "r"(a[2]), "r"(a[3]), "r"(b[0]), "r"(b[1]));
}

// ---------------------------------------------------------------------------
// 1) build_P: P = emb_slice @ W; writes g_P AND split-bf16 A3 [hi|lo];
//    zeroes head/tail. grid 192, block 256, 32 rows/blk.
// ---------------------------------------------------------------------------
__global__ void __launch_bounds__(256) build_P(const float* __restrict__ emb,
                                               const float* __restrict__ W) {
    __shared__ float stage[32 * 66];
    int tid = threadIdx.x;
    int r0  = blockIdx.x * 32;
    int b   = r0 / SLEN;
    int u0  = r0 - b * SLEN;

    float acc[32];
    #pragma unroll
    for (int i = 0; i < 32; ++i) acc[i] = 0.f;

    for (int e0 = 0; e0 < EE; e0 += 64) {
        __syncthreads();
        for (int idx = tid; idx < 32 * 64; idx += 256) {
            int i = idx >> 6, e = idx & 63;
            stage[i * 66 + e] = emb[((b * TT) + 64 + u0 + i) * EE + e0 + e];
        }
        __syncthreads();
        #pragma unroll 4
        for (int e = 0; e < 64; ++e) {
            float w = W[(e0 + e) * CC + tid];
            #pragma unroll
            for (int i = 0; i < 32; ++i) acc[i] += stage[i * 66 + e] * w;
        }
    }
    #pragma unroll
    for (int i = 0; i < 32; ++i) {
        int r = r0 + i;
        float x = acc[i];
        g_P[r * CC + tid] = x;
        __nv_bfloat16 hi = __float2bfloat16(x);
        __nv_bfloat16 lo = __float2bfloat16(x - __bfloat162float(hi));
        size_t base = (size_t)r * K3;
        g_A3[base + tid]       = hi;
        g_A3[base + 256 + tid] = lo;
    }
    if (tid < 32) g_head[r0 + tid] = 0.f;
    for (int t = tid; t < 32 * 11; t += 256) g_tail[r0 * 11 + t] = 0.f;
}

// ---------------------------------------------------------------------------
// 2) split_B: B3 row = [hi(C) | hi(C)] from gathered ctx.
// ---------------------------------------------------------------------------
__global__ void __launch_bounds__(256) split_B(const float* __restrict__ ctx) {
    int c = blockIdx.x, tid = threadIdx.x;
    int j = c / SLEN, v = c - j * SLEN;
    float x = ctx[((j * TT) + 63 + v) * CC + tid];
    __nv_bfloat16 hi = __float2bfloat16(x);
    size_t base = (size_t)c * K3;
    g_B3[base + tid]       = hi;
    g_B3[base + 256 + tid] = hi;
}

// ---------------------------------------------------------------------------
// 3) positives: g_pos[r][s] = dot(P[r], ctx[b][63+u-s]) fp32. 1 warp/row.
// ---------------------------------------------------------------------------
__global__ void __launch_bounds__(256) positives(const float* __restrict__ ctx) {
    int tid = threadIdx.x, wid = tid >> 5, lane = tid & 31;
    int r = blockIdx.x * 8 + wid;
    int b = r / SLEN, u = r - b * SLEN;

    float p[8];
    #pragma unroll
    for (int i = 0; i < 8; ++i) p[i] = g_P[r * CC + lane + i * 32];

    int smax = (u < 11) ? u : 11;
    for (int s = 0; s <= smax; ++s) {
        const float* crow = ctx + ((b * TT) + 63 + (u - s)) * CC;
        float acc = 0.f;
        #pragma unroll
        for (int i = 0; i < 8; ++i) acc += p[i] * crow[lane + i * 32];
        #pragma unroll
        for (int off = 16; off; off >>= 1)
            acc += __shfl_down_sync(0xffffffffu, acc, off);
        if (lane == 0) g_pos[r * NSTEPS + s] = acc;
    }
}

// ---------------------------------------------------------------------------
// 4) gemm_mma: bf16 mma.sync GEMM, KCH=16, 3-stage cp.async (prefetch dist 2),
//    hoisted addressing, 1 sync/chunk. 128x128 tile, 8 warps (2Mx4N).
//    grid (48,48), block 256. smem: 3 x 2 x 128 x 24 x 2 = 36864 B.
// ---------------------------------------------------------------------------
__global__ void __launch_bounds__(256) gemm_mma() {
    __shared__ __nv_bfloat16 sA[NSTG][128 * SST];
    __shared__ __nv_bfloat16 sB[NSTG][128 * SST];

    int tid  = threadIdx.x;
    int wid  = tid >> 5;
    int lane = tid & 31;
    int g    = lane >> 2;
    int tg   = lane & 3;
    int wM   = wid & 1;
    int wN   = wid >> 1;
    int row0 = blockIdx.y * 128;
    int col0 = blockIdx.x * 128;

    // ---- hoisted load addressing: 2 slots/thread (512 x 16B per chunk) ----
    const char* gp[2];
    uint32_t    sa[NSTG][2];
    #pragma unroll
    for (int i = 0; i < 2; ++i) {
        int idx = tid + i * 256;           // 0..511
        int isB = idx >> 8;
        int sub = idx & 255;
        int rr  = sub >> 1;                // 0..127
        int cu  = (sub & 1) * 8;           // bf16 offset
        if (isB == 0) {
            gp[i] = (const char*)&g_A3[(size_t)(row0 + rr) * K3 + cu];
            #pragma unroll
            for (int s = 0; s < NSTG; ++s) sa[s][i] = smem_u32(&sA[s][rr * SST + cu]);
        } else {
            gp[i] = (const char*)&g_B3[(size_t)(col0 + rr) * K3 + cu];
            #pragma unroll
            for (int s = 0; s < NSTG; ++s) sa[s][i] = smem_u32(&sB[s][rr * SST + cu]);
        }
    }

    // ---- hoisted fragment addressing ----
    int lr  = lane & 15;
    int lcb = (lane >> 4) * 8;
    uint32_t aB[NSTG], bB[NSTG];
    #pragma unroll
    for (int s = 0; s < NSTG; ++s) {
        aB[s] = smem_u32(&sA[s][(wM * 64 + lr) * SST + lcb]);
        bB[s] = smem_u32(&sB[s][(wN * 32 + lr) * SST + lcb]);
    }

    float d[4][4][4];
    #pragma unroll
    for (int mi = 0; mi < 4; ++mi)
        #pragma unroll
        for (int ni = 0; ni < 4; ++ni)
            #pragma unroll
            for (int q = 0; q < 4; ++q) d[mi][ni][q] = 0.f;

    // preload chunks 0,1
    #pragma unroll
    for (int i = 0; i < 2; ++i) { CP_ASYNC16(sa[0][i], gp[i]); gp[i] += KCH * 2; }
    CP_COMMIT();
    #pragma unroll
    for (int i = 0; i < 2; ++i) { CP_ASYNC16(sa[1][i], gp[i]); gp[i] += KCH * 2; }
    CP_COMMIT();

    for (int ch = 0; ch < NCH; ++ch) {
        int st = ch % NSTG;
        CP_WAIT1();                         // chunk ch resident; ch+1 may fly
        __syncthreads();                    // all warps past compute(ch-1)
        if (ch + 2 < NCH) {
            int st2 = (ch + 2) % NSTG;
            #pragma unroll
            for (int i = 0; i < 2; ++i) { CP_ASYNC16(sa[st2][i], gp[i]); gp[i] += KCH * 2; }
            CP_COMMIT();
        } else {
            CP_COMMIT();                    // dummy keeps wait arithmetic exact
        }

        uint32_t bfr[2][4];
        #pragma unroll
        for (int pr = 0; pr < 2; ++pr) {
            LDMX4(bfr[pr][0], bfr[pr][1], bfr[pr][2], bfr[pr][3],
                  bB[st] + pr * (16 * SST * 2));
        }
        #pragma unroll
        for (int mi = 0; mi < 4; ++mi) {
            uint32_t afr[4];
            LDMX4(afr[0], afr[1], afr[2], afr[3],
                  aB[st] + mi * (16 * SST * 2));
            #pragma unroll
            for (int pr = 0; pr < 2; ++pr) {
                uint32_t b0[2] = {bfr[pr][0], bfr[pr][2]};
                uint32_t b1[2] = {bfr[pr][1], bfr[pr][3]};
                mma16816(d[mi][pr * 2],     afr, b0);
                mma16816(d[mi][pr * 2 + 1], afr, b1);
            }
        }
    }

    // ---- epilogue: exp + head/tail ----
    float headLo[4] = {0, 0, 0, 0}, headHi[4] = {0, 0, 0, 0};
    #pragma unroll
    for (int mi = 0; mi < 4; ++mi) {
        int rLo = row0 + wM * 64 + mi * 16 + g;
        int rHi = rLo + 8;
        #pragma unroll
        for (int ni = 0; ni < 4; ++ni) {
            int c0c = col0 + wN * 32 + ni * 8 + tg * 2;
            #pragma unroll
            for (int q = 0; q < 2; ++q) {
                int cc = c0c + q;
                int v  = cc % SLEN;
                float eLo = __expf(d[mi][ni][q]     - OFFSET);
                float eHi = __expf(d[mi][ni][q + 2] - OFFSET);
                if (v < 181) { headLo[mi] += eLo; headHi[mi] += eHi; }
                else {
                    atomicAdd(&g_tail[rLo * 11 + (v - 181)], eLo);
                    atomicAdd(&g_tail[rHi * 11 + (v - 181)], eHi);
                }
            }
        }
    }
    #pragma unroll
    for (int mi = 0; mi < 4; ++mi) {
        float lo = headLo[mi], hi = headHi[mi];
        lo += __shfl_down_sync(0xffffffffu, lo, 2, 4);
        lo += __shfl_down_sync(0xffffffffu, lo, 1, 4);
        hi += __shfl_down_sync(0xffffffffu, hi, 2, 4);
        hi += __shfl_down_sync(0xffffffffu, hi, 1, 4);
        if (tg == 0) {
            int rLo = row0 + wM * 64 + mi * 16 + g;
            atomicAdd(&g_head[rLo],     lo);
            atomicAdd(&g_head[rLo + 8], hi);
        }
    }
}

// ---------------------------------------------------------------------------
// 5) finalize: S_s = head + prefix(tails) (addition only). 1024 threads.
// ---------------------------------------------------------------------------
__global__ void __launch_bounds__(1024) finalize(float* __restrict__ out, int out_size) {
    __shared__ double sred[1024];
    __shared__ float slogN[NSTEPS];
    int tid = threadIdx.x;
    if (tid < NSTEPS) slogN[tid] = logf((float)(BATCH * (SLEN - tid)));
    __syncthreads();

    double s = 0.0;
    for (int r = tid; r < NROWS; r += 1024) {
        float hd = g_head[r];
        float pref[12];
        pref[0] = 0.f;
        #pragma unroll
        for (int t = 0; t < 11; ++t) pref[t + 1] = pref[t] + g_tail[r * 11 + t];
        int u = r % SLEN;
        int smax = (u < 11) ? u : 11;
        for (int st = 0; st <= smax; ++st) {
            float S = hd + pref[11 - st];
            float lse = OFFSET + logf(fmaxf(S, 1e-35f)) - slogN[st];
            s += (double)(g_pos[r * NSTEPS + st] - lse);
        }
    }
    sred[tid] = s;
    __syncthreads();
    for (int k = 512; k > 0; k >>= 1) {
        if (tid < k) sred[tid] += sred[tid + k];
        __syncthreads();
    }
    float val = (float)(-sred[0] / TOTAL_COUNT);
    for (int i = tid; i < out_size; i += 1024) out[i] = val;
}

// ---------------------------------------------------------------------------
extern "C" void kernel_launch(void* const* d_in, const int* in_sizes, int n_in,
                              void* d_out, int out_size) {
    int wIdx = -1;
    for (int i = 0; i < n_in; ++i)
        if (in_sizes[i] == EE * CC) { wIdx = i; break; }
    if (wIdx < 0) wIdx = 2;
    int others[2]; int no = 0;
    for (int i = 0; i < n_in && no < 2; ++i)
        if (i != wIdx) others[no++] = i;

    const float* embeddings = (const float*)d_in[others[0]];  // (32,256,256)
    const float* contexts   = (const float*)d_in[others[1]];  // (32,256,256)
    const float* W          = (const float*)d_in[wIdx];       // (256,256)
    float* out = (float*)d_out;

    build_P<<<NROWS / 32, 256>>>(embeddings, W);
    split_B<<<NROWS, 256>>>(contexts);
    positives<<<NROWS / 8, 256>>>(contexts);
    gemm_mma<<<dim3(48, 48), 256>>>();
    finalize<<<1, 1024>>>(out, out_size);
}

// round 16
// speedup vs baseline: 1.7644x; 1.2083x over previous
#include <cuda_runtime.h>
#include <cuda_bf16.h>
#include <math.h>
#include <cstdint>

#define BATCH   32
#define TT      256
#define EE      256
#define CC      256
#define SLEN    192
#define NROWS   (BATCH * SLEN)      // 6144
#define NSTEPS  12
#define KK      256                 // pure hi GEMM (pos is fp32; lse bias ~3e-4 abs)
#define KCH     16
#define NCH     (KK / KCH)          // 16
#define NSTG    3
#define OFFSET  40.0f
#define TOTAL_COUNT 71616.0
#define SST     24                  // smem row stride (bf16): 48B, conflict-free ldmatrix

// ---------------- scratch ----------------
__device__ float          g_P[NROWS * CC];          // fp32 projections (6 MB)
__device__ __nv_bfloat16  g_Ab[(size_t)NROWS * KK]; // 3 MB  hi(P)
__device__ __nv_bfloat16  g_Bb[(size_t)NROWS * KK]; // 3 MB  hi(C)
__device__ float          g_head[NROWS];
__device__ float          g_tail[NROWS * 11];
__device__ float          g_pos [NROWS * NSTEPS];

// ---------------- asm helpers ----------------
#define CP_ASYNC16(sa, gp) \
    asm volatile("cp.async.cg.shared.global [%0], [%1], 16;" :: "r"(sa), "l"(gp))
#define CP_COMMIT() asm volatile("cp.async.commit_group;" ::: "memory")
#define CP_WAIT1()  asm volatile("cp.async.wait_group 1;" ::: "memory")
#define LDMX4(r0, r1, r2, r3, addr) \
    asm volatile("ldmatrix.sync.aligned.m8n8.x4.shared.b16 {%0,%1,%2,%3}, [%4];" \
                 : "=r"(r0), "=r"(r1), "=r"(r2), "=r"(r3) : "r"(addr))

__device__ __forceinline__ uint32_t smem_u32(const void* p) {
    return (uint32_t)__cvta_generic_to_shared(p);
}
__device__ __forceinline__ void mma16816(float* d, const uint32_t* a, const uint32_t* b) {
    asm volatile(
        "mma.sync.aligned.m16n8k16.row.col.f32.bf16.bf16.f32 "
        "{%0,%1,%2,%3}, {%4,%5,%6,%7}, {%8,%9}, {%0,%1,%2,%3};"
        : "+f"(d[0]), "+f"(d[1]), "+f"(d[2]), "+f"(d[3])
        : "r"(a[0]), "r"(a[1]), "r"(a[2]), "r"(a[3]), "r"(b[0]), "r"(b[1]));
}

// ---------------------------------------------------------------------------
// 1) build_P: P = emb_slice @ W; writes g_P and g_Ab = hi(P); zeroes head/tail.
// ---------------------------------------------------------------------------
__global__ void __launch_bounds__(256) build_P(const float* __restrict__ emb,
                                               const float* __restrict__ W) {
    __shared__ float stage[32 * 66];
    int tid = threadIdx.x;
    int r0  = blockIdx.x * 32;
    int b   = r0 / SLEN;
    int u0  = r0 - b * SLEN;

    float acc[32];
    #pragma unroll
    for (int i = 0; i < 32; ++i) acc[i] = 0.f;

    for (int e0 = 0; e0 < EE; e0 += 64) {
        __syncthreads();
        for (int idx = tid; idx < 32 * 64; idx += 256) {
            int i = idx >> 6, e = idx & 63;
            stage[i * 66 + e] = emb[((b * TT) + 64 + u0 + i) * EE + e0 + e];
        }
        __syncthreads();
        #pragma unroll 4
        for (int e = 0; e < 64; ++e) {
            float w = W[(e0 + e) * CC + tid];
            #pragma unroll
            for (int i = 0; i < 32; ++i) acc[i] += stage[i * 66 + e] * w;
        }
    }
    #pragma unroll
    for (int i = 0; i < 32; ++i) {
        int r = r0 + i;
        g_P[r * CC + tid] = acc[i];
        g_Ab[(size_t)r * KK + tid] = __float2bfloat16(acc[i]);
    }
    if (tid < 32) g_head[r0 + tid] = 0.f;
    for (int t = tid; t < 32 * 11; t += 256) g_tail[r0 * 11 + t] = 0.f;
}

// ---------------------------------------------------------------------------
// 2) conv_B: g_Bb = hi(gathered ctx).
// ---------------------------------------------------------------------------
__global__ void __launch_bounds__(256) conv_B(const float* __restrict__ ctx) {
    int c = blockIdx.x, tid = threadIdx.x;
    int j = c / SLEN, v = c - j * SLEN;
    g_Bb[(size_t)c * KK + tid] =
        __float2bfloat16(ctx[((j * TT) + 63 + v) * CC + tid]);
}

// ---------------------------------------------------------------------------
// 3) positives: g_pos[r][s] = dot(P[r], ctx[b][63+u-s]) fp32. 1 warp/row.
// ---------------------------------------------------------------------------
__global__ void __launch_bounds__(256) positives(const float* __restrict__ ctx) {
    int tid = threadIdx.x, wid = tid >> 5, lane = tid & 31;
    int r = blockIdx.x * 8 + wid;
    int b = r / SLEN, u = r - b * SLEN;

    float p[8];
    #pragma unroll
    for (int i = 0; i < 8; ++i) p[i] = g_P[r * CC + lane + i * 32];

    int smax = (u < 11) ? u : 11;
    for (int s = 0; s <= smax; ++s) {
        const float* crow = ctx + ((b * TT) + 63 + (u - s)) * CC;
        float acc = 0.f;
        #pragma unroll
        for (int i = 0; i < 8; ++i) acc += p[i] * crow[lane + i * 32];
        #pragma unroll
        for (int off = 16; off; off >>= 1)
            acc += __shfl_down_sync(0xffffffffu, acc, off);
        if (lane == 0) g_pos[r * NSTEPS + s] = acc;
    }
}

// ---------------------------------------------------------------------------
// 4) gemm_mma: 128x128 tile, 4 warps (2Mx2N, each 64x64), 128 threads.
//    3-stage cp.async, KCH=16, hoisted addressing, 2 CTAs/SM for overlap.
//    grid (48,48). smem: 3 x 2 x 128 x 24 x 2 = 36864 B.
// ---------------------------------------------------------------------------
__global__ void __launch_bounds__(128) gemm_mma() {
    __shared__ __nv_bfloat16 sA[NSTG][128 * SST];
    __shared__ __nv_bfloat16 sB[NSTG][128 * SST];

    int tid  = threadIdx.x;
    int wid  = tid >> 5;
    int lane = tid & 31;
    int g    = lane >> 2;
    int tg   = lane & 3;
    int wM   = wid & 1;            // 64-row half
    int wN   = wid >> 1;           // 64-col half
    int row0 = blockIdx.y * 128;
    int col0 = blockIdx.x * 128;

    // ---- hoisted load addressing: 4 slots/thread (512 x 16B per chunk) ----
    const char* gp[4];
    uint32_t    sa[NSTG][4];
    #pragma unroll
    for (int i = 0; i < 4; ++i) {
        int idx = tid + i * 128;           // 0..511
        int isB = idx >> 8;
        int sub = idx & 255;
        int rr  = sub >> 1;                // 0..127
        int cu  = (sub & 1) * 8;
        if (isB == 0) {
            gp[i] = (const char*)&g_Ab[(size_t)(row0 + rr) * KK + cu];
            #pragma unroll
            for (int s = 0; s < NSTG; ++s) sa[s][i] = smem_u32(&sA[s][rr * SST + cu]);
        } else {
            gp[i] = (const char*)&g_Bb[(size_t)(col0 + rr) * KK + cu];
            #pragma unroll
            for (int s = 0; s < NSTG; ++s) sa[s][i] = smem_u32(&sB[s][rr * SST + cu]);
        }
    }

    // ---- hoisted fragment addressing ----
    int lr  = lane & 15;
    int lcb = (lane >> 4) * 8;
    uint32_t aB[NSTG], bB[NSTG];
    #pragma unroll
    for (int s = 0; s < NSTG; ++s) {
        aB[s] = smem_u32(&sA[s][(wM * 64 + lr) * SST + lcb]);
        bB[s] = smem_u32(&sB[s][(wN * 64 + lr) * SST + lcb]);
    }

    float d[4][8][4];
    #pragma unroll
    for (int mi = 0; mi < 4; ++mi)
        #pragma unroll
        for (int ni = 0; ni < 8; ++ni)
            #pragma unroll
            for (int q = 0; q < 4; ++q) d[mi][ni][q] = 0.f;

    // preload chunks 0,1
    #pragma unroll
    for (int i = 0; i < 4; ++i) { CP_ASYNC16(sa[0][i], gp[i]); gp[i] += KCH * 2; }
    CP_COMMIT();
    #pragma unroll
    for (int i = 0; i < 4; ++i) { CP_ASYNC16(sa[1][i], gp[i]); gp[i] += KCH * 2; }
    CP_COMMIT();

    int st = 0, stP = 2;            // current stage, prefetch stage (rotating)
    for (int ch = 0; ch < NCH; ++ch) {
        CP_WAIT1();
        __syncthreads();
        if (ch + 2 < NCH) {
            #pragma unroll
            for (int i = 0; i < 4; ++i) { CP_ASYNC16(sa[stP][i], gp[i]); gp[i] += KCH * 2; }
            CP_COMMIT();
        } else {
            CP_COMMIT();            // dummy keeps wait arithmetic exact
        }

        uint32_t bfr[4][4];
        #pragma unroll
        for (int pr = 0; pr < 4; ++pr) {
            LDMX4(bfr[pr][0], bfr[pr][1], bfr[pr][2], bfr[pr][3],
                  bB[st] + pr * (16 * SST * 2));
        }
        #pragma unroll
        for (int mi = 0; mi < 4; ++mi) {
            uint32_t afr[4];
            LDMX4(afr[0], afr[1], afr[2], afr[3],
                  aB[st] + mi * (16 * SST * 2));
            #pragma unroll
            for (int pr = 0; pr < 4; ++pr) {
                uint32_t b0[2] = {bfr[pr][0], bfr[pr][2]};
                uint32_t b1[2] = {bfr[pr][1], bfr[pr][3]};
                mma16816(d[mi][pr * 2],     afr, b0);
                mma16816(d[mi][pr * 2 + 1], afr, b1);
            }
        }
        st  = (st  == NSTG - 1) ? 0 : st + 1;
        stP = (stP == NSTG - 1) ? 0 : stP + 1;
    }

    // ---- epilogue: exp + head/tail ----
    float headLo[4] = {0, 0, 0, 0}, headHi[4] = {0, 0, 0, 0};
    #pragma unroll
    for (int mi = 0; mi < 4; ++mi) {
        int rLo = row0 + wM * 64 + mi * 16 + g;
        int rHi = rLo + 8;
        #pragma unroll
        for (int ni = 0; ni < 8; ++ni) {
            int c0c = col0 + wN * 64 + ni * 8 + tg * 2;
            #pragma unroll
            for (int q = 0; q < 2; ++q) {
                int cc = c0c + q;
                int v  = cc % SLEN;
                float eLo = __expf(d[mi][ni][q]     - OFFSET);
                float eHi = __expf(d[mi][ni][q + 2] - OFFSET);
                if (v < 181) { headLo[mi] += eLo; headHi[mi] += eHi; }
                else {
                    atomicAdd(&g_tail[rLo * 11 + (v - 181)], eLo);
                    atomicAdd(&g_tail[rHi * 11 + (v - 181)], eHi);
                }
            }
        }
    }
    #pragma unroll
    for (int mi = 0; mi < 4; ++mi) {
        float lo = headLo[mi], hi = headHi[mi];
        lo += __shfl_down_sync(0xffffffffu, lo, 2, 4);
        lo += __shfl_down_sync(0xffffffffu, lo, 1, 4);
        hi += __shfl_down_sync(0xffffffffu, hi, 2, 4);
        hi += __shfl_down_sync(0xffffffffu, hi, 1, 4);
        if (tg == 0) {
            int rLo = row0 + wM * 64 + mi * 16 + g;
            atomicAdd(&g_head[rLo],     lo);
            atomicAdd(&g_head[rLo + 8], hi);
        }
    }
}

// ---------------------------------------------------------------------------
// 5) finalize: S_s = head + prefix(tails) (addition only). 1024 threads.
// ---------------------------------------------------------------------------
__global__ void __launch_bounds__(1024) finalize(float* __restrict__ out, int out_size) {
    __shared__ double sred[1024];
    __shared__ float slogN[NSTEPS];
    int tid = threadIdx.x;
    if (tid < NSTEPS) slogN[tid] = logf((float)(BATCH * (SLEN - tid)));
    __syncthreads();

    double s = 0.0;
    for (int r = tid; r < NROWS; r += 1024) {
        float hd = g_head[r];
        float pref[12];
        pref[0] = 0.f;
        #pragma unroll
        for (int t = 0; t < 11; ++t) pref[t + 1] = pref[t] + g_tail[r * 11 + t];
        int u = r % SLEN;
        int smax = (u < 11) ? u : 11;
        for (int st = 0; st <= smax; ++st) {
            float S = hd + pref[11 - st];
            float lse = OFFSET + logf(fmaxf(S, 1e-35f)) - slogN[st];
            s += (double)(g_pos[r * NSTEPS + st] - lse);
        }
    }
    sred[tid] = s;
    __syncthreads();
    for (int k = 512; k > 0; k >>= 1) {
        if (tid < k) sred[tid] += sred[tid + k];
        __syncthreads();
    }
    float val = (float)(-sred[0] / TOTAL_COUNT);
    for (int i = tid; i < out_size; i += 1024) out[i] = val;
}

// ---------------------------------------------------------------------------
extern "C" void kernel_launch(void* const* d_in, const int* in_sizes, int n_in,
                              void* d_out, int out_size) {
    int wIdx = -1;
    for (int i = 0; i < n_in; ++i)
        if (in_sizes[i] == EE * CC) { wIdx = i; break; }
    if (wIdx < 0) wIdx = 2;
    int others[2]; int no = 0;
    for (int i = 0; i < n_in && no < 2; ++i)
        if (i != wIdx) others[no++] = i;

    const float* embeddings = (const float*)d_in[others[0]];  // (32,256,256)
    const float* contexts   = (const float*)d_in[others[1]];  // (32,256,256)
    const float* W          = (const float*)d_in[wIdx];       // (256,256)
    float* out = (float*)d_out;

    build_P<<<NROWS / 32, 256>>>(embeddings, W);
    conv_B<<<NROWS, 256>>>(contexts);
    positives<<<NROWS / 8, 256>>>(contexts);
    gemm_mma<<<dim3(48, 48), 128>>>();
    finalize<<<1, 1024>>>(out, out_size);
}

// round 17
// speedup vs baseline: 1.9256x; 1.0914x over previous
#include <cuda_runtime.h>
#include <cuda_bf16.h>
#include <math.h>
#include <cstdint>

#define BATCH   32
#define TT      256
#define EE      256
#define CC      256
#define SLEN    192
#define NROWS   (BATCH * SLEN)      // 6144
#define NSTEPS  12
#define KK      256                 // pure hi-bf16 GEMM (lse bias ~3e-4 abs, rel ~1e-5)
#define KCH     16
#define NCH     (KK / KCH)          // 16
#define NSTG    3
#define OFFSET  40.0f
#define TOTAL_COUNT 71616.0
#define SST     24                  // smem row stride (bf16): 48B, conflict-free ldmatrix

// ---------------- scratch ----------------
__device__ __nv_bfloat16  g_Ab[(size_t)NROWS * KK]; // 3 MB  hi(P)
__device__ __nv_bfloat16  g_Bb[(size_t)NROWS * KK]; // 3 MB  hi(C)
__device__ float          g_head[NROWS];
__device__ float          g_tail[NROWS * 11];
__device__ float          g_pos [NROWS * NSTEPS];

// ---------------- asm helpers ----------------
#define CP_ASYNC16(sa, gp) \
    asm volatile("cp.async.cg.shared.global [%0], [%1], 16;" :: "r"(sa), "l"(gp))
#define CP_COMMIT() asm volatile("cp.async.commit_group;" ::: "memory")
#define CP_WAIT1()  asm volatile("cp.async.wait_group 1;" ::: "memory")
#define LDMX4(r0, r1, r2, r3, addr) \
    asm volatile("ldmatrix.sync.aligned.m8n8.x4.shared.b16 {%0,%1,%2,%3}, [%4];" \
                 : "=r"(r0), "=r"(r1), "=r"(r2), "=r"(r3) : "r"(addr))

__device__ __forceinline__ uint32_t smem_u32(const void* p) {
    return (uint32_t)__cvta_generic_to_shared(p);
}
__device__ __forceinline__ void mma16816(float* d, const uint32_t* a, const uint32_t* b) {
    asm volatile(
        "mma.sync.aligned.m16n8k16.row.col.f32.bf16.bf16.f32 "
        "{%0,%1,%2,%3}, {%4,%5,%6,%7}, {%8,%9}, {%0,%1,%2,%3};"
        : "+f"(d[0]), "+f"(d[1]), "+f"(d[2]), "+f"(d[3])
        : "r"(a[0]), "r"(a[1]), "r"(a[2]), "r"(a[3]), "r"(b[0]), "r"(b[1]));
}

// ---------------------------------------------------------------------------
// 1) build_P_pos: P = emb_slice @ W; writes g_Ab = hi(P); computes positives
//    in-block from smem-staged P; zeroes head/tail. grid 192, block 256.
//    smem: stage 8448 + sP 32x257x4 = 41344 B.
// ---------------------------------------------------------------------------
__global__ void __launch_bounds__(256) build_P_pos(const float* __restrict__ emb,
                                                   const float* __restrict__ W,
                                                   const float* __restrict__ ctx) {
    __shared__ float stage[32 * 66];
    __shared__ float sP[32][257];
    int tid = threadIdx.x;
    int r0  = blockIdx.x * 32;
    int b   = r0 / SLEN;
    int u0  = r0 - b * SLEN;

    float acc[32];
    #pragma unroll
    for (int i = 0; i < 32; ++i) acc[i] = 0.f;

    for (int e0 = 0; e0 < EE; e0 += 64) {
        __syncthreads();
        for (int idx = tid; idx < 32 * 64; idx += 256) {
            int i = idx >> 6, e = idx & 63;
            stage[i * 66 + e] = emb[((b * TT) + 64 + u0 + i) * EE + e0 + e];
        }
        __syncthreads();
        #pragma unroll 4
        for (int e = 0; e < 64; ++e) {
            float w = W[(e0 + e) * CC + tid];
            #pragma unroll
            for (int i = 0; i < 32; ++i) acc[i] += stage[i * 66 + e] * w;
        }
    }
    #pragma unroll
    for (int i = 0; i < 32; ++i) {
        int r = r0 + i;
        g_Ab[(size_t)r * KK + tid] = __float2bfloat16(acc[i]);
        sP[i][tid] = acc[i];
    }
    if (tid < 32) g_head[r0 + tid] = 0.f;
    for (int t = tid; t < 32 * 11; t += 256) g_tail[r0 * 11 + t] = 0.f;
    __syncthreads();

    // positives: warp w handles rows w*4..w*4+3
    int wid = tid >> 5, lane = tid & 31;
    #pragma unroll
    for (int k = 0; k < 4; ++k) {
        int i = wid * 4 + k;
        int u = u0 + i;
        int r = r0 + i;
        int smax = (u < 11) ? u : 11;
        for (int s = 0; s <= smax; ++s) {
            const float* crow = ctx + ((b * TT) + 63 + (u - s)) * CC;
            float a = 0.f;
            #pragma unroll
            for (int q = 0; q < 8; ++q) {
                int ch = lane + q * 32;
                a += sP[i][ch] * crow[ch];
            }
            #pragma unroll
            for (int off = 16; off; off >>= 1)
                a += __shfl_down_sync(0xffffffffu, a, off);
            if (lane == 0) g_pos[r * NSTEPS + s] = a;
        }
    }
}

// ---------------------------------------------------------------------------
// 2) conv_B: g_Bb = hi(gathered ctx).
// ---------------------------------------------------------------------------
__global__ void __launch_bounds__(256) conv_B(const float* __restrict__ ctx) {
    int c = blockIdx.x, tid = threadIdx.x;
    int j = c / SLEN, v = c - j * SLEN;
    g_Bb[(size_t)c * KK + tid] =
        __float2bfloat16(ctx[((j * TT) + 63 + v) * CC + tid]);
}

// ---------------------------------------------------------------------------
// 3) gemm_mma: 128x128 tile, 8 warps (2Mx4N, warp 64x32), 256 threads.
//    KCH=16, 3-stage cp.async (prefetch dist 2), hoisted addressing.
//    grid (48,48). smem: 3 x 2 x 128 x 24 x 2 = 36864 B. ~2 CTAs/SM.
// ---------------------------------------------------------------------------
__global__ void __launch_bounds__(256) gemm_mma() {
    __shared__ __nv_bfloat16 sA[NSTG][128 * SST];
    __shared__ __nv_bfloat16 sB[NSTG][128 * SST];

    int tid  = threadIdx.x;
    int wid  = tid >> 5;
    int lane = tid & 31;
    int g    = lane >> 2;
    int tg   = lane & 3;
    int wM   = wid & 1;
    int wN   = wid >> 1;
    int row0 = blockIdx.y * 128;
    int col0 = blockIdx.x * 128;

    // ---- hoisted load addressing: 2 slots/thread (512 x 16B per chunk) ----
    const char* gp[2];
    uint32_t    sa[NSTG][2];
    #pragma unroll
    for (int i = 0; i < 2; ++i) {
        int idx = tid + i * 256;           // 0..511
        int isB = idx >> 8;
        int sub = idx & 255;
        int rr  = sub >> 1;                // 0..127
        int cu  = (sub & 1) * 8;
        if (isB == 0) {
            gp[i] = (const char*)&g_Ab[(size_t)(row0 + rr) * KK + cu];
            #pragma unroll
            for (int s = 0; s < NSTG; ++s) sa[s][i] = smem_u32(&sA[s][rr * SST + cu]);
        } else {
            gp[i] = (const char*)&g_Bb[(size_t)(col0 + rr) * KK + cu];
            #pragma unroll
            for (int s = 0; s < NSTG; ++s) sa[s][i] = smem_u32(&sB[s][rr * SST + cu]);
        }
    }

    // ---- hoisted fragment addressing ----
    int lr  = lane & 15;
    int lcb = (lane >> 4) * 8;
    uint32_t aB[NSTG], bB[NSTG];
    #pragma unroll
    for (int s = 0; s < NSTG; ++s) {
        aB[s] = smem_u32(&sA[s][(wM * 64 + lr) * SST + lcb]);
        bB[s] = smem_u32(&sB[s][(wN * 32 + lr) * SST + lcb]);
    }

    float d[4][4][4];
    #pragma unroll
    for (int mi = 0; mi < 4; ++mi)
        #pragma unroll
        for (int ni = 0; ni < 4; ++ni)
            #pragma unroll
            for (int q = 0; q < 4; ++q) d[mi][ni][q] = 0.f;

    // preload chunks 0,1
    #pragma unroll
    for (int i = 0; i < 2; ++i) { CP_ASYNC16(sa[0][i], gp[i]); gp[i] += KCH * 2; }
    CP_COMMIT();
    #pragma unroll
    for (int i = 0; i < 2; ++i) { CP_ASYNC16(sa[1][i], gp[i]); gp[i] += KCH * 2; }
    CP_COMMIT();

    int st = 0, stP = 2;
    for (int ch = 0; ch < NCH; ++ch) {
        CP_WAIT1();
        __syncthreads();
        if (ch + 2 < NCH) {
            #pragma unroll
            for (int i = 0; i < 2; ++i) { CP_ASYNC16(sa[stP][i], gp[i]); gp[i] += KCH * 2; }
            CP_COMMIT();
        } else {
            CP_COMMIT();                    // dummy keeps wait arithmetic exact
        }

        uint32_t bfr[2][4];
        #pragma unroll
        for (int pr = 0; pr < 2; ++pr) {
            LDMX4(bfr[pr][0], bfr[pr][1], bfr[pr][2], bfr[pr][3],
                  bB[st] + pr * (16 * SST * 2));
        }
        #pragma unroll
        for (int mi = 0; mi < 4; ++mi) {
            uint32_t afr[4];
            LDMX4(afr[0], afr[1], afr[2], afr[3],
                  aB[st] + mi * (16 * SST * 2));
            #pragma unroll
            for (int pr = 0; pr < 2; ++pr) {
                uint32_t b0[2] = {bfr[pr][0], bfr[pr][2]};
                uint32_t b1[2] = {bfr[pr][1], bfr[pr][3]};
                mma16816(d[mi][pr * 2],     afr, b0);
                mma16816(d[mi][pr * 2 + 1], afr, b1);
            }
        }
        st  = (st  == NSTG - 1) ? 0 : st + 1;
        stP = (stP == NSTG - 1) ? 0 : stP + 1;
    }

    // ---- epilogue: exp + head/tail ----
    float headLo[4] = {0, 0, 0, 0}, headHi[4] = {0, 0, 0, 0};
    #pragma unroll
    for (int mi = 0; mi < 4; ++mi) {
        int rLo = row0 + wM * 64 + mi * 16 + g;
        int rHi = rLo + 8;
        #pragma unroll
        for (int ni = 0; ni < 4; ++ni) {
            int c0c = col0 + wN * 32 + ni * 8 + tg * 2;
            #pragma unroll
            for (int q = 0; q < 2; ++q) {
                int cc = c0c + q;
                int v  = cc % SLEN;
                float eLo = __expf(d[mi][ni][q]     - OFFSET);
                float eHi = __expf(d[mi][ni][q + 2] - OFFSET);
                if (v < 181) { headLo[mi] += eLo; headHi[mi] += eHi; }
                else {
                    atomicAdd(&g_tail[rLo * 11 + (v - 181)], eLo);
                    atomicAdd(&g_tail[rHi * 11 + (v - 181)], eHi);
                }
            }
        }
    }
    #pragma unroll
    for (int mi = 0; mi < 4; ++mi) {
        float lo = headLo[mi], hi = headHi[mi];
        lo += __shfl_down_sync(0xffffffffu, lo, 2, 4);
        lo += __shfl_down_sync(0xffffffffu, lo, 1, 4);
        hi += __shfl_down_sync(0xffffffffu, hi, 2, 4);
        hi += __shfl_down_sync(0xffffffffu, hi, 1, 4);
        if (tg == 0) {
            int rLo = row0 + wM * 64 + mi * 16 + g;
            atomicAdd(&g_head[rLo],     lo);
            atomicAdd(&g_head[rLo + 8], hi);
        }
    }
}

// ---------------------------------------------------------------------------
// 4) finalize: S_s = head + prefix(tails) (addition only). 1024 threads.
// ---------------------------------------------------------------------------
__global__ void __launch_bounds__(1024) finalize(float* __restrict__ out, int out_size) {
    __shared__ double sred[1024];
    __shared__ float slogN[NSTEPS];
    int tid = threadIdx.x;
    if (tid < NSTEPS) slogN[tid] = logf((float)(BATCH * (SLEN - tid)));
    __syncthreads();

    double s = 0.0;
    for (int r = tid; r < NROWS; r += 1024) {
        float hd = g_head[r];
        float pref[12];
        pref[0] = 0.f;
        #pragma unroll
        for (int t = 0; t < 11; ++t) pref[t + 1] = pref[t] + g_tail[r * 11 + t];
        int u = r % SLEN;
        int smax = (u < 11) ? u : 11;
        for (int st = 0; st <= smax; ++st) {
            float S = hd + pref[11 - st];
            float lse = OFFSET + logf(fmaxf(S, 1e-35f)) - slogN[st];
            s += (double)(g_pos[r * NSTEPS + st] - lse);
        }
    }
    sred[tid] = s;
    __syncthreads();
    for (int k = 512; k > 0; k >>= 1) {
        if (tid < k) sred[tid] += sred[tid + k];
        __syncthreads();
    }
    float val = (float)(-sred[0] / TOTAL_COUNT);
    for (int i = tid; i < out_size; i += 1024) out[i] = val;
}

// ---------------------------------------------------------------------------
extern "C" void kernel_launch(void* const* d_in, const int* in_sizes, int n_in,
                              void* d_out, int out_size) {
    int wIdx = -1;
    for (int i = 0; i < n_in; ++i)
        if (in_sizes[i] == EE * CC) { wIdx = i; break; }
    if (wIdx < 0) wIdx = 2;
    int others[2]; int no = 0;
    for (int i = 0; i < n_in && no < 2; ++i)
        if (i != wIdx) others[no++] = i;

    const float* embeddings = (const float*)d_in[others[0]];  // (32,256,256)
    const float* contexts   = (const float*)d_in[others[1]];  // (32,256,256)
    const float* W          = (const float*)d_in[wIdx];       // (256,256)
    float* out = (float*)d_out;

    conv_B<<<NROWS, 256>>>(contexts);
    build_P_pos<<<NROWS / 32, 256>>>(embeddings, W, contexts);
    gemm_mma<<<dim3(48, 48), 256>>>();
    finalize<<<1, 1024>>>(out, out_size);
}